// round 2
// baseline (speedup 1.0000x reference)
#include <cuda_runtime.h>

// out[b,i,j,o] = bias[o] + sum_{th,tw,c} x[b, i-1-th, j-1-tw, c] * K[o,c,th,tw]
// (exact linear-algebra reduction of the rfft2/irfft2 + roll + slice reference;
//  FFT size 128 >= 66 so there is no circular wraparound.)

#define BATCH 8
#define HH 64
#define WW 64
#define CIN 64
#define FF 64

#define XS_STRIDE 67
#define XS_FLOATS (3 * 64 * XS_STRIDE)   // 12864 floats: 3 input rows, [c][col(+3 pad)]
#define WS_FLOATS (3 * CIN * FF)         // 12288 floats: one th-slice, [tw][c][f]
#define SMEM_BYTES ((XS_FLOATS + WS_FLOATS) * 4)

typedef unsigned long long u64;

__device__ __forceinline__ u64 pk2(float lo, float hi) {
    u64 r;
    asm("mov.b64 %0, {%1, %2};" : "=l"(r) : "f"(lo), "f"(hi));
    return r;
}
__device__ __forceinline__ u64 ffma2(u64 a, u64 b, u64 c) {
    u64 d;
    asm("fma.rn.f32x2 %0, %1, %2, %3;" : "=l"(d) : "l"(a), "l"(b), "l"(c));
    return d;
}
__device__ __forceinline__ float2 upk(u64 a) {
    float2 v;
    asm("mov.b64 {%0, %1}, %2;" : "=f"(v.x), "=f"(v.y) : "l"(a));
    return v;
}

// Rearranged weights: [th][tw][c][f], contiguous per-th 48KB slices.
__device__ float g_wre[9 * CIN * FF];

__global__ void wre_kernel(const float* __restrict__ kin) {
    int idx = blockIdx.x * blockDim.x + threadIdx.x;
    if (idx >= 9 * CIN * FF) return;
    int f    = idx & 63;
    int c    = (idx >> 6) & 63;
    int twth = idx >> 12;          // th*3 + tw
    int tw   = twth % 3;
    int th   = twth / 3;
    g_wre[idx] = kin[((f * CIN + c) * 3 + th) * 3 + tw];
}

__global__ __launch_bounds__(256, 2)
void conv_main(const float* __restrict__ x,
               const float* __restrict__ bias,
               float* __restrict__ out) {
    extern __shared__ float sm[];
    float* xs = sm;               // [3][64][XS_STRIDE], col index = 3 + j (left zero pad)
    float* ws = sm + XS_FLOATS;   // [tw][c][f]

    const int tid = threadIdx.x;
    const int b = blockIdx.x >> 6;
    const int i = blockIdx.x & 63;

    // Zero-fill input stage (covers left pad and rows < 0)
    for (int idx = tid; idx < XS_FLOATS; idx += 256) xs[idx] = 0.0f;
    __syncthreads();

    // Stage 3 input rows (i-1, i-2, i-3), transposing NHWC -> [c][col]
    {
        const int c4 = tid & 15;        // c block (4 channels)
        const int j0 = tid >> 4;        // 0..15
        for (int t = 0; t < 3; ++t) {
            int r = i - 1 - t;
            if (r < 0) continue;
            const float4* src = (const float4*)(x + ((size_t)(b * HH + r) * WW) * CIN);
            #pragma unroll
            for (int jj = 0; jj < 4; ++jj) {
                int j = jj * 16 + j0;
                float4 v = src[j * (CIN / 4) + c4];
                int base = (t * 64 + 4 * c4) * XS_STRIDE + 3 + j;
                xs[base]                 = v.x;
                xs[base + XS_STRIDE]     = v.y;
                xs[base + 2 * XS_STRIDE] = v.z;
                xs[base + 3 * XS_STRIDE] = v.w;
            }
        }
    }

    // Accumulators: acc[p][q] = f32x2 over filter pair (f0+2q, f0+2q+1), pixel p in {pp, pp+32}
    u64 acc[2][4];
    #pragma unroll
    for (int p = 0; p < 2; ++p)
        #pragma unroll
        for (int q = 0; q < 4; ++q) acc[p][q] = 0ull;

    const int pp = tid & 31;          // low pixel; high pixel = pp + 32
    const int f0 = (tid >> 5) * 8;    // 8 filters per thread

    for (int th = 0; th < 3; ++th) {
        __syncthreads();  // previous ws consumers done (and xs staging visible on th=0)
        {   // load this th's weight slice, fully coalesced (48KB contiguous)
            const float4* src = (const float4*)(g_wre + th * WS_FLOATS);
            float4* dst = (float4*)ws;
            #pragma unroll
            for (int k = 0; k < 12; ++k) dst[tid + 256 * k] = src[tid + 256 * k];
        }
        __syncthreads();

        const float* xbase = xs + th * 64 * XS_STRIDE + pp;
        const float* wbase = ws + f0;

        #pragma unroll 4
        for (int c = 0; c < 64; ++c) {
            const float* xr = xbase + c * XS_STRIDE;
            // smem col = j + 2 - tw  (x col j-1-tw). Need cols pp..pp+2 and pp+32..pp+34.
            float xl0 = xr[0],  xl1 = xr[1],  xl2 = xr[2];
            float xh0 = xr[32], xh1 = xr[33], xh2 = xr[34];
            const float* wp = wbase + c * 64;
            #pragma unroll
            for (int tw = 0; tw < 3; ++tw) {
                float lx = (tw == 0) ? xl2 : ((tw == 1) ? xl1 : xl0);
                float hx = (tw == 0) ? xh2 : ((tw == 1) ? xh1 : xh0);
                u64 Xl = pk2(lx, lx);
                u64 Xh = pk2(hx, hx);
                const u64* w2 = (const u64*)(wp + tw * (CIN * FF));
                u64 w01 = w2[0], w23 = w2[1], w45 = w2[2], w67 = w2[3];
                acc[0][0] = ffma2(Xl, w01, acc[0][0]);
                acc[0][1] = ffma2(Xl, w23, acc[0][1]);
                acc[0][2] = ffma2(Xl, w45, acc[0][2]);
                acc[0][3] = ffma2(Xl, w67, acc[0][3]);
                acc[1][0] = ffma2(Xh, w01, acc[1][0]);
                acc[1][1] = ffma2(Xh, w23, acc[1][1]);
                acc[1][2] = ffma2(Xh, w45, acc[1][2]);
                acc[1][3] = ffma2(Xh, w67, acc[1][3]);
            }
        }
    }

    // Epilogue: add bias, write NHWC output (two float4 per pixel)
    float bo[8];
    #pragma unroll
    for (int u = 0; u < 8; ++u) bo[u] = bias[f0 + u];

    #pragma unroll
    for (int p = 0; p < 2; ++p) {
        int j = pp + 32 * p;
        float2 v0 = upk(acc[p][0]);
        float2 v1 = upk(acc[p][1]);
        float2 v2 = upk(acc[p][2]);
        float2 v3 = upk(acc[p][3]);
        float* o = out + ((size_t)(b * HH + i) * WW + j) * FF + f0;
        float4 lo = make_float4(v0.x + bo[0], v0.y + bo[1], v1.x + bo[2], v1.y + bo[3]);
        float4 hi = make_float4(v2.x + bo[4], v2.y + bo[5], v3.x + bo[6], v3.y + bo[7]);
        ((float4*)o)[0] = lo;
        ((float4*)o)[1] = hi;
    }
}

extern "C" void kernel_launch(void* const* d_in, const int* in_sizes, int n_in,
                              void* d_out, int out_size) {
    const float* x    = (const float*)d_in[0];
    const float* kern = (const float*)d_in[1];
    const float* bias = (const float*)d_in[2];
    float* out = (float*)d_out;

    cudaFuncSetAttribute(conv_main, cudaFuncAttributeMaxDynamicSharedMemorySize, SMEM_BYTES);

    wre_kernel<<<(9 * CIN * FF + 255) / 256, 256>>>(kern);
    conv_main<<<BATCH * HH, 256, SMEM_BYTES>>>(x, bias, out);
}

// round 3
// speedup vs baseline: 1.0815x; 1.0815x over previous
#include <cuda_runtime.h>

// out[b,i,j,o] = bias[o] + sum_{th,tw,c} x[b, i-1-th, j-1-tw, c] * K[o,c,th,tw]
// (exact linear-algebra reduction of the rfft2/irfft2 + roll + slice reference;
//  FFT size 128 >= 66 so there is no circular wraparound.)

#define BATCH 8
#define HH 64
#define WW 64
#define CIN 64
#define FF 64

#define XSTR 72                          // padded staged-row stride (floats), 16B-multiple
#define XS_FLOATS (3 * CIN * XSTR)       // 13824 floats: 3 input rows, [t][c][col(+4 pad)]
#define WS_FLOATS (3 * CIN * FF)         // 12288 floats: one th-slice, [tw][c][f]
#define SMEM_BYTES ((XS_FLOATS + WS_FLOATS) * 4)

typedef unsigned long long u64;

__device__ __forceinline__ u64 pk2dup(float v) {
    u64 r;
    asm("mov.b64 %0, {%1, %1};" : "=l"(r) : "f"(v));
    return r;
}
__device__ __forceinline__ u64 ffma2(u64 a, u64 b, u64 c) {
    u64 d;
    asm("fma.rn.f32x2 %0, %1, %2, %3;" : "=l"(d) : "l"(a), "l"(b), "l"(c));
    return d;
}
__device__ __forceinline__ float2 upk(u64 a) {
    float2 v;
    asm("mov.b64 {%0, %1}, %2;" : "=f"(v.x), "=f"(v.y) : "l"(a));
    return v;
}

// Rearranged weights: [th][tw][c][f], contiguous per-th 48KB slices.
__device__ float g_wre[9 * CIN * FF];

__global__ void wre_kernel(const float* __restrict__ kin) {
    int idx = blockIdx.x * blockDim.x + threadIdx.x;
    if (idx >= 9 * CIN * FF) return;
    int f    = idx & 63;
    int c    = (idx >> 6) & 63;
    int twth = idx >> 12;          // th*3 + tw
    int tw   = twth % 3;
    int th   = twth / 3;
    g_wre[idx] = kin[((f * CIN + c) * 3 + th) * 3 + tw];
}

__global__ __launch_bounds__(256, 2)
void conv_main(const float* __restrict__ x,
               const float* __restrict__ bias,
               float* __restrict__ out) {
    extern __shared__ float sm[];
    float* xs = sm;               // [3][64][XSTR]; smem col s = input col + 4 (s<4 is zero pad)
    float* ws = sm + XS_FLOATS;   // [tw][c][f]

    const int tid = threadIdx.x;
    const int b = blockIdx.x >> 6;
    const int i = blockIdx.x & 63;

    // Zero-fill input stage (covers left pad and rows < 0)
    for (int idx = tid; idx < XS_FLOATS; idx += 256) xs[idx] = 0.0f;
    __syncthreads();

    // Stage 3 input rows (i-1, i-2, i-3), transposing NHWC -> [c][col]
    {
        const int c4  = tid & 15;       // channel block (4 channels)
        const int j0s = tid >> 4;       // 0..15
        for (int t = 0; t < 3; ++t) {
            int r = i - 1 - t;
            if (r < 0) continue;
            const float4* src = (const float4*)(x + ((size_t)(b * HH + r) * WW) * CIN);
            #pragma unroll
            for (int jj = 0; jj < 4; ++jj) {
                int j = jj * 16 + j0s;
                float4 v = src[j * (CIN / 4) + c4];
                int base = (t * CIN + 4 * c4) * XSTR + 4 + j;
                xs[base]            = v.x;
                xs[base + XSTR]     = v.y;
                xs[base + 2 * XSTR] = v.z;
                xs[base + 3 * XSTR] = v.w;
            }
        }
    }

    // Thread mapping: lane = filter pair (f = 2*lane, 2*lane+1), warp = 8-pixel group.
    const int lane = tid & 31;
    const int j0   = (tid >> 5) * 8;   // pixels j0 .. j0+7

    u64 acc[8];
    #pragma unroll
    for (int p = 0; p < 8; ++p) acc[p] = 0ull;

    for (int th = 0; th < 3; ++th) {
        __syncthreads();  // previous ws consumers done (and xs staging visible on th=0)
        {   // load this th's weight slice, fully coalesced (48KB contiguous)
            const float4* src = (const float4*)(g_wre + th * WS_FLOATS);
            float4* dst = (float4*)ws;
            #pragma unroll
            for (int k = 0; k < 12; ++k) dst[tid + 256 * k] = src[tid + 256 * k];
        }
        __syncthreads();

        const float* xbase = xs + (th * CIN) * XSTR + j0;
        const u64*   wb    = (const u64*)ws;   // index ((tw*CIN + c)*32 + lane)

        #pragma unroll 2
        for (int c = 0; c < CIN; ++c) {
            // 12 warp-uniform x values (smem cols j0 .. j0+11), 3 broadcast LDS.128
            const float* xr = xbase + c * XSTR;
            float4 xa = *(const float4*)(xr);
            float4 xb = *(const float4*)(xr + 4);
            float4 xc = *(const float4*)(xr + 8);
            float xv[12] = {xa.x, xa.y, xa.z, xa.w,
                            xb.x, xb.y, xb.z, xb.w,
                            xc.x, xc.y, xc.z, xc.w};

            // per-lane filter-pair weights for the 3 tw taps (conflict-free LDS.64)
            u64 w0 = wb[(0 * CIN + c) * 32 + lane];   // tw = 0
            u64 w1 = wb[(1 * CIN + c) * 32 + lane];   // tw = 1
            u64 w2 = wb[(2 * CIN + c) * 32 + lane];   // tw = 2

            // pixel j0+p, tap tw reads smem col (j0+p) + 3 - tw  ->  xv[p+3-tw]
            #pragma unroll
            for (int p = 0; p < 8; ++p) {
                acc[p] = ffma2(pk2dup(xv[p + 3]), w0, acc[p]);
                acc[p] = ffma2(pk2dup(xv[p + 2]), w1, acc[p]);
                acc[p] = ffma2(pk2dup(xv[p + 1]), w2, acc[p]);
            }
        }
    }

    // Epilogue: add bias, coalesced float2 stores (warp covers all 64 filters)
    float2 bb = ((const float2*)bias)[lane];

    float* obase = out + ((size_t)(b * HH + i) * WW + j0) * FF + 2 * lane;
    #pragma unroll
    for (int p = 0; p < 8; ++p) {
        float2 v = upk(acc[p]);
        float2 r;
        r.x = v.x + bb.x;
        r.y = v.y + bb.y;
        *(float2*)(obase + (size_t)p * FF) = r;
    }
}

extern "C" void kernel_launch(void* const* d_in, const int* in_sizes, int n_in,
                              void* d_out, int out_size) {
    const float* x    = (const float*)d_in[0];
    const float* kern = (const float*)d_in[1];
    const float* bias = (const float*)d_in[2];
    float* out = (float*)d_out;

    cudaFuncSetAttribute(conv_main, cudaFuncAttributeMaxDynamicSharedMemorySize, SMEM_BYTES);

    wre_kernel<<<(9 * CIN * FF + 255) / 256, 256>>>(kern);
    conv_main<<<BATCH * HH, 256, SMEM_BYTES>>>(x, bias, out);
}

// round 5
// speedup vs baseline: 2.5010x; 2.3125x over previous
#include <cuda_runtime.h>
#include <cstdint>

// out[b,i,j,o] = bias[o] + sum_{th,tw,c} x[b, i-1-th, j-1-tw, c] * K[o,c,th,tw]
// (exact linear reduction of the rfft2/irfft2+roll+slice reference; validated rel_err 4.6e-7 R2/R3)
// Round 4: TF32 mma.sync (m16n8k8) implicit GEMM — sm_100-plain compatible (no tcgen05/TMA).

#define BATCH 8
#define HH 64
#define WW 64
#define CIN 64
#define FF 64

#define STR 68                         // padded row stride (floats): 4 mod 32 -> conflict-free frags
#define XS_FLOATS (4 * 64 * STR)       // 17408: 4 input rows [t][c][s], s = col+3 (zero pad)
#define WS_FLOATS (9 * 64 * STR)       // 39168: weights [tap][f][c-padded]
#define BIAS_OFF  (XS_FLOATS + WS_FLOATS)
#define SMEM_FLOATS (BIAS_OFF + 64)
#define SMEM_BYTES (SMEM_FLOATS * 4)   // 226816 B < 227KB opt-in

__device__ __forceinline__ uint32_t f2tf32(float f) {
    uint32_t r;
    asm("cvt.rna.tf32.f32 %0, %1;" : "=r"(r) : "f"(f));
    return r;
}

__device__ __forceinline__ void mma8(float* d, const uint32_t* a, const uint32_t* b) {
    asm volatile("mma.sync.aligned.m16n8k8.row.col.f32.tf32.tf32.f32 "
                 "{%0,%1,%2,%3}, {%4,%5,%6,%7}, {%8,%9}, {%0,%1,%2,%3};"
                 : "+f"(d[0]), "+f"(d[1]), "+f"(d[2]), "+f"(d[3])
                 : "r"(a[0]), "r"(a[1]), "r"(a[2]), "r"(a[3]), "r"(b[0]), "r"(b[1]));
}

// Repacked, tf32-rounded weights: [tap][f][c], tap = th*3+tw
__device__ float g_w2[9 * FF * CIN];

__global__ void wre2_kernel(const float* __restrict__ kin) {
    int idx = blockIdx.x * blockDim.x + threadIdx.x;
    if (idx >= 9 * FF * CIN) return;
    int c   = idx & 63;
    int f   = (idx >> 6) & 63;
    int tap = idx >> 12;
    int th = tap / 3, tw = tap % 3;
    g_w2[idx] = __uint_as_float(f2tf32(kin[((f * CIN + c) * 3 + th) * 3 + tw]));
}

__global__ __launch_bounds__(256, 1)
void conv_mma(const float* __restrict__ x,
              const float* __restrict__ bias,
              float* __restrict__ out) {
    extern __shared__ float sm[];
    float* xs    = sm;                 // [4][64][STR]
    float* ws    = sm + XS_FLOATS;     // [(tap*64+f)][STR]
    float* sbias = sm + BIAS_OFF;

    const int tid = threadIdx.x;
    const int b  = blockIdx.x >> 5;
    const int i0 = (blockIdx.x & 31) * 2;     // 2 output rows per CTA

    for (int k = tid; k < XS_FLOATS; k += 256) xs[k] = 0.0f;
    if (tid < 64) sbias[tid] = bias[tid];
    __syncthreads();

    // Stage 4 input rows (i0-3 .. i0), NHWC -> [t][c][s], tf32-rounded
    {
        const int c4  = tid & 15;
        const int j0s = tid >> 4;
        for (int t = 0; t < 4; ++t) {
            int row = i0 - 3 + t;
            if (row < 0) continue;
            const float4* src = (const float4*)(x + ((size_t)(b * HH + row) * WW) * CIN);
            #pragma unroll
            for (int jj = 0; jj < 4; ++jj) {
                int j = jj * 16 + j0s;
                float4 v = src[j * (CIN / 4) + c4];
                int base = (t * 64 + 4 * c4) * STR + 3 + j;
                xs[base]           = __uint_as_float(f2tf32(v.x));
                xs[base + STR]     = __uint_as_float(f2tf32(v.y));
                xs[base + 2 * STR] = __uint_as_float(f2tf32(v.z));
                xs[base + 3 * STR] = __uint_as_float(f2tf32(v.w));
            }
        }
    }
    // Stage all 9 tap weight slices (already tf32-rounded), float4, 16B-aligned dsts
    {
        const float4* src = (const float4*)g_w2;
        #pragma unroll
        for (int k = 0; k < 36; ++k) {
            int idx = tid + 256 * k;
            int fi = idx >> 4;       // tap*64 + f
            int c4 = idx & 15;
            *(float4*)(ws + fi * STR + 4 * c4) = src[idx];
        }
    }
    __syncthreads();

    const int lane = tid & 31, wid = tid >> 5;
    const int lq = lane >> 2, lr = lane & 3;
    const int warp_m = wid >> 1;             // 0..3 -> 32-pixel group
    const int n0 = (wid & 1) * 32;           // filter half
    const int pbase = warp_m * 32;
    const int r  = pbase >> 6;               // output-row within CTA (0 or 1)
    const int jb = pbase & 63;               // column base (0 or 32)

    float acc[2][4][4];
    #pragma unroll
    for (int mt = 0; mt < 2; ++mt)
        #pragma unroll
        for (int nt = 0; nt < 4; ++nt)
            #pragma unroll
            for (int q = 0; q < 4; ++q) acc[mt][nt][q] = 0.0f;

    #pragma unroll
    for (int tap = 0; tap < 9; ++tap) {
        const int th = tap / 3, tw = tap % 3;
        // A: pixel (r, j) tap (th,tw) -> xs[t = r+2-th][c][s = j+2-tw]
        const float* xa = xs + ((r + 2 - th) * 64) * STR + (jb + 2 - tw) + lq;
        const float* wb = ws + ((size_t)(tap * 64 + n0 + lq)) * STR + lr;

        #pragma unroll
        for (int c8 = 0; c8 < 8; ++c8) {
            const int cb = c8 * 8 + lr;
            const float* xp = xa + cb * STR;

            uint32_t a0[4], a1[4];
            a0[0] = __float_as_uint(xp[0]);
            a0[1] = __float_as_uint(xp[8]);
            a0[2] = __float_as_uint(xp[4 * STR]);
            a0[3] = __float_as_uint(xp[4 * STR + 8]);
            a1[0] = __float_as_uint(xp[16]);
            a1[1] = __float_as_uint(xp[24]);
            a1[2] = __float_as_uint(xp[4 * STR + 16]);
            a1[3] = __float_as_uint(xp[4 * STR + 24]);

            const float* wp = wb + c8 * 8;
            uint32_t bf[4][2];
            #pragma unroll
            for (int nt = 0; nt < 4; ++nt) {
                bf[nt][0] = __float_as_uint(wp[nt * 8 * STR]);
                bf[nt][1] = __float_as_uint(wp[nt * 8 * STR + 4]);
            }

            #pragma unroll
            for (int nt = 0; nt < 4; ++nt) {
                mma8(acc[0][nt], a0, bf[nt]);
                mma8(acc[1][nt], a1, bf[nt]);
            }
        }
    }

    // Epilogue: bias + store. acc rows = pixel lq (+8), cols = 2*lr (+1)
    const int i = i0 + r;
    #pragma unroll
    for (int mt = 0; mt < 2; ++mt) {
        int j = jb + mt * 16 + lq;
        float* o0 = out + (((size_t)(b * HH + i) * WW + j) * FF);
        float* o1 = o0 + 8 * FF;            // pixel +8: same row, j+8
        #pragma unroll
        for (int nt = 0; nt < 4; ++nt) {
            int f = n0 + nt * 8 + 2 * lr;
            float2 v0 = make_float2(acc[mt][nt][0] + sbias[f], acc[mt][nt][1] + sbias[f + 1]);
            float2 v1 = make_float2(acc[mt][nt][2] + sbias[f], acc[mt][nt][3] + sbias[f + 1]);
            *(float2*)(o0 + f) = v0;
            *(float2*)(o1 + f) = v1;
        }
    }
}

extern "C" void kernel_launch(void* const* d_in, const int* in_sizes, int n_in,
                              void* d_out, int out_size) {
    const float* x    = (const float*)d_in[0];
    const float* kern = (const float*)d_in[1];
    const float* bias = (const float*)d_in[2];
    float* out = (float*)d_out;

    cudaFuncSetAttribute(conv_mma, cudaFuncAttributeMaxDynamicSharedMemorySize, SMEM_BYTES);

    wre2_kernel<<<(9 * FF * CIN + 255) / 256, 256>>>(kern);
    conv_mma<<<BATCH * 32, 256, SMEM_BYTES>>>(x, bias, out);
}

// round 6
// speedup vs baseline: 3.2749x; 1.3095x over previous
#include <cuda_runtime.h>
#include <cstdint>

// out[b,i,j,o] = bias[o] + sum_{th,tw,c} x[b, i-1-th, j-1-tw, c] * K[o,c,th,tw]
// TF32 mma.sync implicit GEMM, ldmatrix fragments, cp.async double-buffered weights,
// 2 CTAs/SM, single wave.

#define BATCH 8
#define HH 64
#define WW 64
#define CIN 64
#define FF 64

#define CSTR 68                         // c-stride per s-row (64 + 4 pad): conflict-free ldmatrix
#define SROWS 68                        // s rows per staged input row (s = col+3, 0..66)
#define XS_FLOATS (4 * SROWS * CSTR)    // 18496 floats: 4 input rows [t][s][c]
#define WBUF_FLOATS (FF * CSTR)         // 4352 floats per weight tap buffer
#define WS_OFF XS_FLOATS
#define BIAS_OFF (WS_OFF + 2 * WBUF_FLOATS)
#define SMEM_FLOATS (BIAS_OFF + 64)
#define SMEM_BYTES (SMEM_FLOATS * 4)    // 109056 B -> 2 CTAs/SM

__device__ __forceinline__ uint32_t f2tf32(float f) {
    uint32_t r;
    asm("cvt.rna.tf32.f32 %0, %1;" : "=r"(r) : "f"(f));
    return r;
}
__device__ __forceinline__ uint32_t smem_u32(const void* p) {
    uint32_t a;
    asm("{ .reg .u64 t; cvta.to.shared.u64 t, %1; cvt.u32.u64 %0, t; }" : "=r"(a) : "l"(p));
    return a;
}
__device__ __forceinline__ void ldsm4(uint32_t* r, uint32_t addr) {
    asm volatile("ldmatrix.sync.aligned.m8n8.x4.shared.b16 {%0,%1,%2,%3}, [%4];"
                 : "=r"(r[0]), "=r"(r[1]), "=r"(r[2]), "=r"(r[3]) : "r"(addr));
}
__device__ __forceinline__ void mma8(float* d, const uint32_t* a, const uint32_t* b) {
    asm volatile("mma.sync.aligned.m16n8k8.row.col.f32.tf32.tf32.f32 "
                 "{%0,%1,%2,%3}, {%4,%5,%6,%7}, {%8,%9}, {%0,%1,%2,%3};"
                 : "+f"(d[0]), "+f"(d[1]), "+f"(d[2]), "+f"(d[3])
                 : "r"(a[0]), "r"(a[1]), "r"(a[2]), "r"(a[3]), "r"(b[0]), "r"(b[1]));
}
__device__ __forceinline__ void cp16(uint32_t dst, const float* src) {
    asm volatile("cp.async.cg.shared.global [%0], [%1], 16;"
                 :: "r"(dst), "l"(__cvta_generic_to_global(src)) : "memory");
}
#define CP_COMMIT() asm volatile("cp.async.commit_group;" ::: "memory")
#define CP_WAIT1()  asm volatile("cp.async.wait_group 1;" ::: "memory")
#define CP_WAIT0()  asm volatile("cp.async.wait_group 0;" ::: "memory")

// Repacked tf32-rounded weights: [tap][f][c], tap = th*3+tw
__device__ float g_w2[9 * FF * CIN];

__global__ void wre2_kernel(const float* __restrict__ kin) {
    int idx = blockIdx.x * blockDim.x + threadIdx.x;
    if (idx >= 9 * FF * CIN) return;
    int c   = idx & 63;
    int f   = (idx >> 6) & 63;
    int tap = idx >> 12;
    int th = tap / 3, tw = tap % 3;
    g_w2[idx] = __uint_as_float(f2tf32(kin[((f * CIN + c) * 3 + th) * 3 + tw]));
}

__global__ __launch_bounds__(256, 2)
void conv_mma(const float* __restrict__ x,
              const float* __restrict__ bias,
              float* __restrict__ out) {
    extern __shared__ float sm[];
    float* xs    = sm;                  // [4][SROWS][CSTR]
    float* sbias = sm + BIAS_OFF;
    const uint32_t sb     = smem_u32(sm);
    const uint32_t sb_ws  = sb + WS_OFF * 4;

    const int tid = threadIdx.x;
    const int b  = blockIdx.x >> 5;
    const int i0 = (blockIdx.x & 31) * 2;     // 2 output rows per CTA

    // zero xs (covers all padding), load bias
    {
        float4 z = make_float4(0.f, 0.f, 0.f, 0.f);
        float4* p = (float4*)xs;
        for (int k = tid; k < XS_FLOATS / 4; k += 256) p[k] = z;
        if (tid < 64) sbias[tid] = bias[tid];
    }
    __syncthreads();

    // Stage 4 input rows (i0-3 .. i0) pixel-major: xs[t][s=j+3][c], tf32-rounded
    {
        const int c4 = tid & 15;        // 4-channel chunk
        const int jh = tid >> 4;        // 0..15
        for (int t = 0; t < 4; ++t) {
            int row = i0 - 3 + t;
            if (row < 0) continue;
            const float4* src = (const float4*)(x + ((size_t)(b * HH + row) * WW) * CIN);
            #pragma unroll
            for (int jj = 0; jj < 4; ++jj) {
                int j = jj * 16 + jh;
                float4 v = src[j * (CIN / 4) + c4];
                float4 w;
                w.x = __uint_as_float(f2tf32(v.x));
                w.y = __uint_as_float(f2tf32(v.y));
                w.z = __uint_as_float(f2tf32(v.z));
                w.w = __uint_as_float(f2tf32(v.w));
                *(float4*)(xs + ((size_t)(t * SROWS + j + 3) * CSTR) + 4 * c4) = w;
            }
        }
    }

    // Weight tap loader (cp.async, 16KB per tap, 4 chunks/thread)
    auto issueW = [&](int tap) {
        uint32_t dbase = sb_ws + (uint32_t)(tap & 1) * (WBUF_FLOATS * 4);
        const float* s0 = g_w2 + tap * (FF * CIN);
        #pragma unroll
        for (int k = 0; k < 4; ++k) {
            int ch = tid + 256 * k;         // 1024 16B-chunks
            int f  = ch >> 4;
            int c4 = ch & 15;
            cp16(dbase + (uint32_t)(f * CSTR + 4 * c4) * 4, s0 + f * CIN + 4 * c4);
        }
        CP_COMMIT();
    };
    issueW(0);
    issueW(1);

    // Warp tiling: 8 warps = 4 m-groups (32 pixels) x 2 n-groups (32 filters)
    const int lane = tid & 31, wid = tid >> 5;
    const int lq = lane >> 2, lr = lane & 3;
    const int wm = wid >> 1;
    const int n0 = (wid & 1) * 32;
    const int r  = wm >> 1;             // output row within CTA
    const int jb = (wm & 1) * 32;       // column base

    // ldmatrix lane address components
    const int sA = lane & 15;                     // A: pixel offset within m16
    const int cA = 4 * (lane >> 4);               // A: k half
    const int fB = (lane & 7) + 8 * (lane >> 4);  // B: filter row within n16
    const int cB = 4 * ((lane >> 3) & 1);         // B: k half

    float acc[2][4][4];
    #pragma unroll
    for (int mt = 0; mt < 2; ++mt)
        #pragma unroll
        for (int nt = 0; nt < 4; ++nt)
            #pragma unroll
            for (int q = 0; q < 4; ++q) acc[mt][nt][q] = 0.0f;

    for (int tap = 0; tap < 9; ++tap) {
        if (tap < 8) CP_WAIT1(); else CP_WAIT0();
        __syncthreads();                 // weights for this tap visible to all warps

        const int th = tap / 3, tw = tap - 3 * th;
        const int trow = r + 2 - th;
        const int s0 = jb + 2 - tw;

        uint32_t aA0 = sb + (uint32_t)(((trow * SROWS) + s0 + sA) * CSTR + cA) * 4;
        uint32_t aA1 = aA0 + (uint32_t)(16 * CSTR) * 4;
        uint32_t wbase = sb_ws + (uint32_t)(tap & 1) * (WBUF_FLOATS * 4);
        uint32_t aB0 = wbase + (uint32_t)((n0 + fB) * CSTR + cB) * 4;
        uint32_t aB1 = aB0 + (uint32_t)(16 * CSTR) * 4;

        #pragma unroll
        for (int c8 = 0; c8 < 8; ++c8) {
            uint32_t a0[4], a1[4], b0[4], b1[4];
            ldsm4(a0, aA0); ldsm4(a1, aA1);
            ldsm4(b0, aB0); ldsm4(b1, aB1);
            aA0 += 32; aA1 += 32; aB0 += 32; aB1 += 32;

            mma8(acc[0][0], a0, b0);     mma8(acc[1][0], a1, b0);
            mma8(acc[0][1], a0, b0 + 2); mma8(acc[1][1], a1, b0 + 2);
            mma8(acc[0][2], a0, b1);     mma8(acc[1][2], a1, b1);
            mma8(acc[0][3], a0, b1 + 2); mma8(acc[1][3], a1, b1 + 2);
        }

        __syncthreads();                 // all warps done reading this tap's buffer
        if (tap + 2 < 9) issueW(tap + 2);
    }

    // Epilogue: bias + store. acc rows = pixel lq (+8), cols = 2*lr (+1)
    const int i = i0 + r;
    #pragma unroll
    for (int mt = 0; mt < 2; ++mt) {
        int j = jb + mt * 16 + lq;
        float* o0 = out + (((size_t)(b * HH + i) * WW + j) * FF);
        float* o1 = o0 + 8 * FF;          // pixel +8
        #pragma unroll
        for (int nt = 0; nt < 4; ++nt) {
            int f = n0 + nt * 8 + 2 * lr;
            float2 v0 = make_float2(acc[mt][nt][0] + sbias[f], acc[mt][nt][1] + sbias[f + 1]);
            float2 v1 = make_float2(acc[mt][nt][2] + sbias[f], acc[mt][nt][3] + sbias[f + 1]);
            *(float2*)(o0 + f) = v0;
            *(float2*)(o1 + f) = v1;
        }
    }
}

extern "C" void kernel_launch(void* const* d_in, const int* in_sizes, int n_in,
                              void* d_out, int out_size) {
    const float* x    = (const float*)d_in[0];
    const float* kern = (const float*)d_in[1];
    const float* bias = (const float*)d_in[2];
    float* out = (float*)d_out;

    cudaFuncSetAttribute(conv_mma, cudaFuncAttributeMaxDynamicSharedMemorySize, SMEM_BYTES);

    wre2_kernel<<<(9 * FF * CIN + 255) / 256, 256>>>(kern);
    conv_mma<<<BATCH * 32, 256, SMEM_BYTES>>>(x, bias, out);
}

// round 7
// speedup vs baseline: 4.2898x; 1.3099x over previous
#include <cuda_runtime.h>
#include <cuda_fp16.h>
#include <cstdint>

// out[b,i,j,o] = bias[o] + sum_{th,tw,c} x[b, i-1-th, j-1-tw, c] * K[o,c,th,tw]
// fp16 m16n8k16 mma.sync implicit GEMM (fp32 accum), ldmatrix frags,
// 4-deep cp.async weight pipeline, 2 CTAs/SM, single wave.

#define BATCH 8
#define HH 64
#define WW 64
#define CIN 64
#define FF 64

#define CSTRH 72                         // fp16 per s-row (64 + 8 pad): 144B stride, conflict-free
#define SROWSH 67                        // s = input col + 3 (0..66)
#define XS_HALFS (4 * SROWSH * CSTRH)    // 19296 halfs
#define WBUF_HALFS (FF * CSTRH)          // 4608 halfs per tap buffer
#define NBUF 4
#define WS_OFF XS_HALFS
#define BIAS_OFF_H (WS_OFF + NBUF * WBUF_HALFS)   // f32 bias after (half-index, 4B aligned: even)
#define SMEM_BYTES ((BIAS_OFF_H) * 2 + 64 * 4)    // 75968 B -> 2 CTAs/SM

__device__ __forceinline__ uint32_t smem_u32(const void* p) {
    uint32_t a;
    asm("{ .reg .u64 t; cvta.to.shared.u64 t, %1; cvt.u32.u64 %0, t; }" : "=r"(a) : "l"(p));
    return a;
}
__device__ __forceinline__ void ldsm4(uint32_t* r, uint32_t addr) {
    asm volatile("ldmatrix.sync.aligned.m8n8.x4.shared.b16 {%0,%1,%2,%3}, [%4];"
                 : "=r"(r[0]), "=r"(r[1]), "=r"(r[2]), "=r"(r[3]) : "r"(addr));
}
__device__ __forceinline__ void mma16(float* d, const uint32_t* a, uint32_t b0, uint32_t b1) {
    asm volatile("mma.sync.aligned.m16n8k16.row.col.f32.f16.f16.f32 "
                 "{%0,%1,%2,%3}, {%4,%5,%6,%7}, {%8,%9}, {%0,%1,%2,%3};"
                 : "+f"(d[0]), "+f"(d[1]), "+f"(d[2]), "+f"(d[3])
                 : "r"(a[0]), "r"(a[1]), "r"(a[2]), "r"(a[3]), "r"(b0), "r"(b1));
}
__device__ __forceinline__ void cp16(uint32_t dst, const void* src) {
    asm volatile("cp.async.cg.shared.global [%0], [%1], 16;"
                 :: "r"(dst), "l"(__cvta_generic_to_global(src)) : "memory");
}
#define CP_COMMIT() asm volatile("cp.async.commit_group;" ::: "memory")
#define CP_WAIT(n)  asm volatile("cp.async.wait_group %0;" :: "n"(n) : "memory")

// Repacked fp16 weights: [tap][f][c], tap = th*3+tw  (8KB per tap, contiguous)
__device__ __half g_w3[9 * FF * CIN];

__global__ void wre3_kernel(const float* __restrict__ kin) {
    int idx = blockIdx.x * blockDim.x + threadIdx.x;
    if (idx >= 9 * FF * CIN) return;
    int c   = idx & 63;
    int f   = (idx >> 6) & 63;
    int tap = idx >> 12;
    int th = tap / 3, tw = tap % 3;
    g_w3[idx] = __float2half_rn(kin[((f * CIN + c) * 3 + th) * 3 + tw]);
}

__global__ __launch_bounds__(256, 2)
void conv_mma(const float* __restrict__ x,
              const float* __restrict__ bias,
              float* __restrict__ out) {
    extern __shared__ __half smh[];
    __half* xs    = smh;                        // [4][SROWSH][CSTRH]
    float*  sbias = (float*)(smh + BIAS_OFF_H);
    const uint32_t sb    = smem_u32(smh);
    const uint32_t sb_ws = sb + WS_OFF * 2;

    const int tid = threadIdx.x;
    const int b  = blockIdx.x >> 5;
    const int i0 = (blockIdx.x & 31) * 2;       // 2 output rows per CTA

    // Weight pipeline: 4 buffers, commit one group per tap
    auto issueW = [&](int tap) {
        uint32_t dbase = sb_ws + (uint32_t)(tap & 3) * (WBUF_HALFS * 2);
        const __half* s0 = g_w3 + tap * (FF * CIN);
        #pragma unroll
        for (int k = 0; k < 2; ++k) {
            int ch = tid + 256 * k;             // 512 chunks of 16B (8 fp16)
            int f  = ch >> 3;
            int k8 = ch & 7;
            cp16(dbase + (uint32_t)(f * CSTRH + 8 * k8) * 2, s0 + f * CIN + 8 * k8);
        }
        CP_COMMIT();
    };
    issueW(0); issueW(1); issueW(2); issueW(3);

    // Zero pad s-rows 0..2 of every t-plane (left border), and negative-row planes
    {
        uint2 z = make_uint2(0u, 0u);
        // 4 t-planes x 3 rows x 72 halfs = 864 halfs = 216 uint2 (rows are 8B-aligned: 144B stride)
        if (tid < 216) {
            int t = tid / 54, rr = tid % 54;    // rr: 3 rows x 18 uint2
            int s = rr / 18, q = rr % 18;
            *(uint2*)(xs + (t * SROWSH + s) * CSTRH + 4 * q) = z;
        }
        int nneg = (i0 == 0) ? 3 : (i0 == 2 ? 1 : 0);
        for (int t = 0; t < nneg; ++t) {
            uint2* p = (uint2*)(xs + t * SROWSH * CSTRH);
            for (int k = tid; k < SROWSH * CSTRH / 4; k += 256) p[k] = z;
        }
    }

    // Stage 4 input rows (i0-3 .. i0) pixel-major fp16: xs[t][s=j+3][c]
    {
        const int c4 = tid & 15;
        const int jh = tid >> 4;
        for (int t = 0; t < 4; ++t) {
            int row = i0 - 3 + t;
            if (row < 0) continue;
            const float4* src = (const float4*)(x + ((size_t)(b * HH + row) * WW) * CIN);
            #pragma unroll
            for (int jj = 0; jj < 4; ++jj) {
                int j = jj * 16 + jh;
                float4 v = src[j * (CIN / 4) + c4];
                __half2 h0 = __float22half2_rn(make_float2(v.x, v.y));
                __half2 h1 = __float22half2_rn(make_float2(v.z, v.w));
                uint2 w;
                w.x = *(uint32_t*)&h0;
                w.y = *(uint32_t*)&h1;
                *(uint2*)(xs + (size_t)(t * SROWSH + j + 3) * CSTRH + 4 * c4) = w;
            }
        }
        if (tid < 64) sbias[tid] = bias[tid];
    }

    // Warp tiling: 8 warps = 4 m-groups (32 pixels) x 2 n-groups (32 filters)
    const int lane = tid & 31, wid = tid >> 5;
    const int lq = lane >> 2, lr = lane & 3;
    const int wm = wid >> 1;
    const int n0 = (wid & 1) * 32;
    const int r  = wm >> 1;                     // output row within CTA
    const int jb = (wm & 1) * 32;               // column base

    // ldmatrix lane pointer components (b16, 16B per lane)
    const int mA = lane & 15;                   // A: pixel row within m16
    const int kA = 8 * (lane >> 4);             // A: k half (fp16 units)
    const int fB = (lane & 7) + 8 * ((lane >> 3) & 1);
    const int kB = 8 * (lane >> 4);

    float acc[2][4][4];
    #pragma unroll
    for (int mt = 0; mt < 2; ++mt)
        #pragma unroll
        for (int nt = 0; nt < 4; ++nt)
            #pragma unroll
            for (int q = 0; q < 4; ++q) acc[mt][nt][q] = 0.0f;

    for (int tap = 0; tap < 9; ++tap) {
        if (tap < 6) { CP_WAIT(2); } else { CP_WAIT(0); }
        __syncthreads();                        // tap data visible; prior tap fully consumed
        if (tap >= 1 && tap + 3 <= 8) issueW(tap + 3);

        const int th = tap / 3, tw = tap - 3 * th;
        const int trow = r + 2 - th;
        const int s0 = jb + 2 - tw;

        uint32_t aA0 = sb + (uint32_t)(((trow * SROWSH) + s0 + mA) * CSTRH + kA) * 2;
        uint32_t aA1 = aA0 + (uint32_t)(16 * CSTRH) * 2;
        uint32_t wb  = sb_ws + (uint32_t)(tap & 3) * (WBUF_HALFS * 2);
        uint32_t aB0 = wb + (uint32_t)((n0 + fB) * CSTRH + kB) * 2;
        uint32_t aB1 = aB0 + (uint32_t)(16 * CSTRH) * 2;

        #pragma unroll
        for (int ks = 0; ks < 4; ++ks) {        // K = 64 = 4 x k16
            uint32_t a0[4], a1[4], b0[4], b1[4];
            ldsm4(a0, aA0); ldsm4(a1, aA1);
            ldsm4(b0, aB0); ldsm4(b1, aB1);
            aA0 += 32; aA1 += 32; aB0 += 32; aB1 += 32;   // +16 fp16 in k

            // B frag for n8 tile f0-7 = {r0, r2}; f8-15 = {r1, r3}
            mma16(acc[0][0], a0, b0[0], b0[2]); mma16(acc[1][0], a1, b0[0], b0[2]);
            mma16(acc[0][1], a0, b0[1], b0[3]); mma16(acc[1][1], a1, b0[1], b0[3]);
            mma16(acc[0][2], a0, b1[0], b1[2]); mma16(acc[1][2], a1, b1[0], b1[2]);
            mma16(acc[0][3], a0, b1[1], b1[3]); mma16(acc[1][3], a1, b1[1], b1[3]);
        }
    }

    // Epilogue: bias + store. acc rows = pixel lq (+8), cols = 2*lr (+1)
    const int i = i0 + r;
    #pragma unroll
    for (int mt = 0; mt < 2; ++mt) {
        int j = jb + mt * 16 + lq;
        float* o0 = out + (((size_t)(b * HH + i) * WW + j) * FF);
        float* o1 = o0 + 8 * FF;                // pixel +8
        #pragma unroll
        for (int nt = 0; nt < 4; ++nt) {
            int f = n0 + nt * 8 + 2 * lr;
            float2 v0 = make_float2(acc[mt][nt][0] + sbias[f], acc[mt][nt][1] + sbias[f + 1]);
            float2 v1 = make_float2(acc[mt][nt][2] + sbias[f], acc[mt][nt][3] + sbias[f + 1]);
            *(float2*)(o0 + f) = v0;
            *(float2*)(o1 + f) = v1;
        }
    }
}

extern "C" void kernel_launch(void* const* d_in, const int* in_sizes, int n_in,
                              void* d_out, int out_size) {
    const float* x    = (const float*)d_in[0];
    const float* kern = (const float*)d_in[1];
    const float* bias = (const float*)d_in[2];
    float* out = (float*)d_out;

    cudaFuncSetAttribute(conv_mma, cudaFuncAttributeMaxDynamicSharedMemorySize, SMEM_BYTES);

    wre3_kernel<<<(9 * FF * CIN + 255) / 256, 256>>>(kern);
    conv_mma<<<BATCH * 32, 256, SMEM_BYTES>>>(x, bias, out);
}

// round 9
// speedup vs baseline: 4.8049x; 1.1201x over previous
#include <cuda_runtime.h>
#include <cuda_fp16.h>
#include <cstdint>

// out[b,i,j,o] = bias[o] + sum_{th,tw,c} x[b, i-1-th, j-1-tw, c] * K[o,c,th,tw]
// fp16 m16n8k16 mma.sync implicit GEMM (fp32 accum). All 9 tap weight slices smem-resident
// (XOR-swizzled 128B rows), barrier-free fully-unrolled mainloop, 2 CTAs/SM, single wave.

#define BATCH 8
#define HH 64
#define WW 64
#define CIN 64
#define FF 64

#define SROWSH 67                         // s = input col + 3 (0..66)
// x: 4 planes x 67 rows x 128B (swizzled chunks)  = 34304 B
// w: 9 taps  x 64 rows x 128B (swizzled chunks)   = 73728 B
#define XS_BYTES (4 * SROWSH * 128)
#define WS_BYTE_OFF XS_BYTES
#define BIAS_BYTE_OFF (XS_BYTES + 9 * FF * 128)
#define SMEM_BYTES (BIAS_BYTE_OFF + 64 * 4)       // 108288 B -> 2 CTAs/SM

__device__ __forceinline__ uint32_t smem_u32(const void* p) {
    uint32_t a;
    asm("{ .reg .u64 t; cvta.to.shared.u64 t, %1; cvt.u32.u64 %0, t; }" : "=r"(a) : "l"(p));
    return a;
}
__device__ __forceinline__ void ldsm4(uint32_t* r, uint32_t addr) {
    asm volatile("ldmatrix.sync.aligned.m8n8.x4.shared.b16 {%0,%1,%2,%3}, [%4];"
                 : "=r"(r[0]), "=r"(r[1]), "=r"(r[2]), "=r"(r[3]) : "r"(addr));
}
__device__ __forceinline__ void mma16(float* d, const uint32_t* a, uint32_t b0, uint32_t b1) {
    asm volatile("mma.sync.aligned.m16n8k16.row.col.f32.f16.f16.f32 "
                 "{%0,%1,%2,%3}, {%4,%5,%6,%7}, {%8,%9}, {%0,%1,%2,%3};"
                 : "+f"(d[0]), "+f"(d[1]), "+f"(d[2]), "+f"(d[3])
                 : "r"(a[0]), "r"(a[1]), "r"(a[2]), "r"(a[3]), "r"(b0), "r"(b1));
}
__device__ __forceinline__ void cp16(uint32_t dst, const void* src) {
    asm volatile("cp.async.cg.shared.global [%0], [%1], 16;"
                 :: "r"(dst), "l"(__cvta_generic_to_global(src)) : "memory");
}
#define CP_COMMIT() asm volatile("cp.async.commit_group;" ::: "memory")
#define CP_WAIT0()  asm volatile("cp.async.wait_group 0;" ::: "memory")

// Repacked fp16 weights: [tap][f][c], tap = th*3+tw  (8KB per tap, contiguous)
__device__ __half g_w3[9 * FF * CIN];

__global__ void wre3_kernel(const float* __restrict__ kin) {
    int idx = blockIdx.x * blockDim.x + threadIdx.x;
    if (idx >= 9 * FF * CIN) return;
    int c   = idx & 63;
    int f   = (idx >> 6) & 63;
    int tap = idx >> 12;
    int th = tap / 3, tw = tap % 3;
    g_w3[idx] = __float2half_rn(kin[((f * CIN + c) * 3 + th) * 3 + tw]);
}

__global__ __launch_bounds__(256, 2)
void conv_mma(const float* __restrict__ x,
              const float* __restrict__ bias,
              float* __restrict__ out) {
    extern __shared__ char smc[];
    const uint32_t sb    = smem_u32(smc);
    const uint32_t sb_ws = sb + WS_BYTE_OFF;
    float* sbias = (float*)(smc + BIAS_BYTE_OFF);

    const int tid = threadIdx.x;
    const int b  = blockIdx.x >> 5;
    const int i0 = (blockIdx.x & 31) * 2;       // 2 output rows per CTA

    // ---- all 9 weight tap slices via cp.async (4608 x 16B chunks, XOR-swizzled) ----
    #pragma unroll
    for (int k = 0; k < 18; ++k) {
        int ch = tid + 256 * k;                 // 0..4607
        int fr = ch >> 3;                       // tap*64 + f  (0..575)
        int k8 = ch & 7;                        // 16B chunk within row
        cp16(sb_ws + (uint32_t)(fr * 128 + ((k8 ^ (fr & 7)) << 4)),
             g_w3 + fr * 64 + k8 * 8);
    }
    CP_COMMIT();

    // ---- zero padding rows (swizzle is a within-row permutation; whole-row zero is fine) ----
    {
        uint4 z = make_uint4(0u, 0u, 0u, 0u);
        // left-pad rows s=0..2 of each t-plane: 4 planes x 384B = 96 x 16B
        if (tid < 96) {
            int t = tid / 24, q = tid % 24;
            *(uint4*)(smc + t * (SROWSH * 128) + q * 16) = z;
        }
        // negative input rows: whole planes
        int nneg = (i0 == 0) ? 3 : (i0 == 2 ? 1 : 0);
        if (nneg) {
            uint4* p = (uint4*)smc;
            for (int k = tid; k < nneg * SROWSH * 8; k += 256) p[k] = z;
        }
    }

    // ---- stage 4 input rows (i0-3 .. i0) pixel-major fp16, swizzled ----
    {
        const int c4 = tid & 15;                // 4-channel chunk (8B of fp16)
        const int jh = tid >> 4;                // 0..15
        const int sub = (c4 & 1) * 8;           // 8B half within 16B chunk
        for (int t = 0; t < 4; ++t) {
            int row = i0 - 3 + t;
            if (row < 0) continue;
            const float4* src = (const float4*)(x + ((size_t)(b * HH + row) * WW) * CIN);
            #pragma unroll
            for (int jj = 0; jj < 4; ++jj) {
                int j = jj * 16 + jh;
                float4 v = src[j * (CIN / 4) + c4];
                __half2 h0 = __float22half2_rn(make_float2(v.x, v.y));
                __half2 h1 = __float22half2_rn(make_float2(v.z, v.w));
                uint2 w;
                w.x = *(uint32_t*)&h0;
                w.y = *(uint32_t*)&h1;
                int rowid = t * SROWSH + j + 3;
                *(uint2*)(smc + rowid * 128 + (((c4 >> 1) ^ (rowid & 7)) << 4) + sub) = w;
            }
        }
        if (tid < 64) sbias[tid] = bias[tid];
    }

    CP_WAIT0();
    __syncthreads();                            // ONE barrier; mainloop is barrier-free

    // ---- warp tiling: 8 warps = 4 m-groups (32 px) x 2 n-groups (32 filters) ----
    const int lane = tid & 31, wid = tid >> 5;
    const int lq = lane >> 2, lr = lane & 3;
    const int wm = wid >> 1;
    const int n0 = (wid & 1) * 32;
    const int r  = wm >> 1;
    const int jb = (wm & 1) * 32;

    const int mA  = lane & 15;                  // A row within m16
    const int kcA = lane >> 4;                  // A 16B k-chunk parity
    const int fB  = (lane & 7) + 8 * ((lane >> 3) & 1);
    const int kcB = lane >> 4;

    // B row bases (per tap add tap*8192); swizzle keys constant across taps
    const uint32_t rbB0 = sb_ws + (uint32_t)((n0 + fB) * 128);
    const uint32_t rbB1 = rbB0 + 16 * 128;
    const int sB = fB & 7;                      // n0, +16 are multiples of 8

    float acc[2][4][4];
    #pragma unroll
    for (int mt = 0; mt < 2; ++mt)
        #pragma unroll
        for (int nt = 0; nt < 4; ++nt)
            #pragma unroll
            for (int q = 0; q < 4; ++q) acc[mt][nt][q] = 0.0f;

    #pragma unroll
    for (int tap = 0; tap < 9; ++tap) {
        const int th = tap / 3, tw = tap - 3 * th;
        const int rowA0 = (r + 2 - th) * SROWSH + (jb + 2 - tw) + mA;
        const int rowA1 = rowA0 + 16;
        const uint32_t rbA0 = sb + (uint32_t)(rowA0 * 128);
        const uint32_t rbA1 = sb + (uint32_t)(rowA1 * 128);
        const int sA = rowA0 & 7;               // rowA1 has same low3 bits
        const uint32_t wt = (uint32_t)(tap * 8192);

        #pragma unroll
        for (int ks = 0; ks < 4; ++ks) {        // K = 64 = 4 x k16
            const int ca = (2 * ks + kcA);
            const int cb = (2 * ks + kcB);
            uint32_t a0[4], a1[4], b0[4], b1[4];
            ldsm4(a0, rbA0 + ((ca ^ sA) << 4));
            ldsm4(a1, rbA1 + ((ca ^ sA) << 4));
            ldsm4(b0, rbB0 + wt + ((cb ^ sB) << 4));
            ldsm4(b1, rbB1 + wt + ((cb ^ sB) << 4));

            mma16(acc[0][0], a0, b0[0], b0[2]); mma16(acc[1][0], a1, b0[0], b0[2]);
            mma16(acc[0][1], a0, b0[1], b0[3]); mma16(acc[1][1], a1, b0[1], b0[3]);
            mma16(acc[0][2], a0, b1[0], b1[2]); mma16(acc[1][2], a1, b1[0], b1[2]);
            mma16(acc[0][3], a0, b1[1], b1[3]); mma16(acc[1][3], a1, b1[1], b1[3]);
        }
    }

    // ---- epilogue: bias + store. acc rows = pixel lq (+8), cols = 2*lr (+1) ----
    const int i = i0 + r;
    #pragma unroll
    for (int mt = 0; mt < 2; ++mt) {
        int j = jb + mt * 16 + lq;
        float* o0 = out + (((size_t)(b * HH + i) * WW + j) * FF);
        float* o1 = o0 + 8 * FF;                // pixel +8
        #pragma unroll
        for (int nt = 0; nt < 4; ++nt) {
            int f = n0 + nt * 8 + 2 * lr;
            float2 v0 = make_float2(acc[mt][nt][0] + sbias[f], acc[mt][nt][1] + sbias[f + 1]);
            float2 v1 = make_float2(acc[mt][nt][2] + sbias[f], acc[mt][nt][3] + sbias[f + 1]);
            *(float2*)(o0 + f) = v0;
            *(float2*)(o1 + f) = v1;
        }
    }
}

extern "C" void kernel_launch(void* const* d_in, const int* in_sizes, int n_in,
                              void* d_out, int out_size) {
    const float* x    = (const float*)d_in[0];
    const float* kern = (const float*)d_in[1];
    const float* bias = (const float*)d_in[2];
    float* out = (float*)d_out;

    cudaFuncSetAttribute(conv_mma, cudaFuncAttributeMaxDynamicSharedMemorySize, SMEM_BYTES);

    wre3_kernel<<<(9 * FF * CIN + 255) / 256, 256>>>(kern);
    conv_mma<<<BATCH * 32, 256, SMEM_BYTES>>>(x, bias, out);
}

// round 10
// speedup vs baseline: 4.9922x; 1.0390x over previous
#include <cuda_runtime.h>
#include <cuda_fp16.h>
#include <cstdint>

// out[b,i,j,o] = bias[o] + sum_{th,tw,c} x[b, i-1-th, j-1-tw, c] * K[o,c,th,tw]
// fp16 m16n8k16 mma.sync implicit GEMM (fp32 accum). All 9 tap weight slices smem-resident
// (XOR-swizzled 128B rows). Flat 36-step mainloop with 1-deep register fragment prefetch.

#define BATCH 8
#define HH 64
#define WW 64
#define CIN 64
#define FF 64

#define SROWSH 67                         // s = input col + 3 (0..66)
#define XS_BYTES (4 * SROWSH * 128)
#define WS_BYTE_OFF XS_BYTES
#define BIAS_BYTE_OFF (XS_BYTES + 9 * FF * 128)
#define SMEM_BYTES (BIAS_BYTE_OFF + 64 * 4)       // 108288 B -> 2 CTAs/SM

__device__ __forceinline__ uint32_t smem_u32(const void* p) {
    uint32_t a;
    asm("{ .reg .u64 t; cvta.to.shared.u64 t, %1; cvt.u32.u64 %0, t; }" : "=r"(a) : "l"(p));
    return a;
}
__device__ __forceinline__ void ldsm4(uint32_t* r, uint32_t addr) {
    asm volatile("ldmatrix.sync.aligned.m8n8.x4.shared.b16 {%0,%1,%2,%3}, [%4];"
                 : "=r"(r[0]), "=r"(r[1]), "=r"(r[2]), "=r"(r[3]) : "r"(addr));
}
__device__ __forceinline__ void mma16(float* d, const uint32_t* a, uint32_t b0, uint32_t b1) {
    asm volatile("mma.sync.aligned.m16n8k16.row.col.f32.f16.f16.f32 "
                 "{%0,%1,%2,%3}, {%4,%5,%6,%7}, {%8,%9}, {%0,%1,%2,%3};"
                 : "+f"(d[0]), "+f"(d[1]), "+f"(d[2]), "+f"(d[3])
                 : "r"(a[0]), "r"(a[1]), "r"(a[2]), "r"(a[3]), "r"(b0), "r"(b1));
}
__device__ __forceinline__ void cp16(uint32_t dst, const void* src) {
    asm volatile("cp.async.cg.shared.global [%0], [%1], 16;"
                 :: "r"(dst), "l"(__cvta_generic_to_global(src)) : "memory");
}
#define CP_COMMIT() asm volatile("cp.async.commit_group;" ::: "memory")
#define CP_WAIT0()  asm volatile("cp.async.wait_group 0;" ::: "memory")

// Repacked fp16 weights: [tap][f][c], tap = th*3+tw  (8KB per tap, contiguous)
__device__ __half g_w3[9 * FF * CIN];

__global__ void wre3_kernel(const float* __restrict__ kin) {
    int idx = blockIdx.x * blockDim.x + threadIdx.x;
    if (idx >= 9 * FF * CIN) return;
    int c   = idx & 63;
    int f   = (idx >> 6) & 63;
    int tap = idx >> 12;
    int th = tap / 3, tw = tap % 3;
    g_w3[idx] = __float2half_rn(kin[((f * CIN + c) * 3 + th) * 3 + tw]);
}

__global__ __launch_bounds__(256, 2)
void conv_mma(const float* __restrict__ x,
              const float* __restrict__ bias,
              float* __restrict__ out) {
    extern __shared__ char smc[];
    const uint32_t sb    = smem_u32(smc);
    const uint32_t sb_ws = sb + WS_BYTE_OFF;
    float* sbias = (float*)(smc + BIAS_BYTE_OFF);

    const int tid = threadIdx.x;
    const int b  = blockIdx.x >> 5;
    const int i0 = (blockIdx.x & 31) * 2;       // 2 output rows per CTA

    // ---- all 9 weight tap slices via cp.async (4608 x 16B chunks, XOR-swizzled) ----
    #pragma unroll
    for (int k = 0; k < 18; ++k) {
        int ch = tid + 256 * k;                 // 0..4607
        int fr = ch >> 3;                       // tap*64 + f  (0..575)
        int k8 = ch & 7;                        // 16B chunk within row
        cp16(sb_ws + (uint32_t)(fr * 128 + ((k8 ^ (fr & 7)) << 4)),
             g_w3 + fr * 64 + k8 * 8);
    }
    CP_COMMIT();

    // ---- zero padding rows (swizzle is a within-row permutation; whole-row zero is fine) ----
    {
        uint4 z = make_uint4(0u, 0u, 0u, 0u);
        if (tid < 96) {
            int t = tid / 24, q = tid % 24;
            *(uint4*)(smc + t * (SROWSH * 128) + q * 16) = z;
        }
        int nneg = (i0 == 0) ? 3 : (i0 == 2 ? 1 : 0);
        if (nneg) {
            uint4* p = (uint4*)smc;
            for (int k = tid; k < nneg * SROWSH * 8; k += 256) p[k] = z;
        }
    }

    // ---- stage 4 input rows (i0-3 .. i0) pixel-major fp16, swizzled ----
    {
        const int c4 = tid & 15;
        const int jh = tid >> 4;
        const int sub = (c4 & 1) * 8;
        for (int t = 0; t < 4; ++t) {
            int row = i0 - 3 + t;
            if (row < 0) continue;
            const float4* src = (const float4*)(x + ((size_t)(b * HH + row) * WW) * CIN);
            #pragma unroll
            for (int jj = 0; jj < 4; ++jj) {
                int j = jj * 16 + jh;
                float4 v = src[j * (CIN / 4) + c4];
                __half2 h0 = __float22half2_rn(make_float2(v.x, v.y));
                __half2 h1 = __float22half2_rn(make_float2(v.z, v.w));
                uint2 w;
                w.x = *(uint32_t*)&h0;
                w.y = *(uint32_t*)&h1;
                int rowid = t * SROWSH + j + 3;
                *(uint2*)(smc + rowid * 128 + (((c4 >> 1) ^ (rowid & 7)) << 4) + sub) = w;
            }
        }
        if (tid < 64) sbias[tid] = bias[tid];
    }

    CP_WAIT0();
    __syncthreads();                            // ONE barrier; mainloop is barrier-free

    // ---- warp tiling: 8 warps = 4 m-groups (32 px) x 2 n-groups (32 filters) ----
    const int lane = tid & 31, wid = tid >> 5;
    const int lq = lane >> 2, lr = lane & 3;
    const int wm = wid >> 1;
    const int n0 = (wid & 1) * 32;
    const int r  = wm >> 1;
    const int jb = (wm & 1) * 32;

    const int mA  = lane & 15;                  // A row within m16
    const int kcA = lane >> 4;                  // A 16B k-chunk parity
    const int fB  = (lane & 7) + 8 * ((lane >> 3) & 1);
    const int kcB = lane >> 4;

    const uint32_t rbB0 = sb_ws + (uint32_t)((n0 + fB) * 128);
    const uint32_t rbB1 = rbB0 + 16 * 128;
    const int sB = fB & 7;

    float acc[2][4][4];
    #pragma unroll
    for (int mt = 0; mt < 2; ++mt)
        #pragma unroll
        for (int nt = 0; nt < 4; ++nt)
            #pragma unroll
            for (int q = 0; q < 4; ++q) acc[mt][nt][q] = 0.0f;

    // ---- flat 36-step mainloop (tap = it>>2, ks = it&3), 1-deep fragment prefetch ----
    uint32_t fa[2][2][4];                       // [buf][m-tile][regs]
    uint32_t fb[2][2][4];                       // [buf][n16-tile][regs]

    auto ldfrag = [&](int it, int pb) {
        const int tap = it >> 2, ks = it & 3;
        const int th = tap / 3, tw = tap - 3 * th;
        const int rowA0 = (r + 2 - th) * SROWSH + (jb + 2 - tw) + mA;
        const uint32_t rbA0 = sb + (uint32_t)(rowA0 * 128);
        const int sA = rowA0 & 7;
        const uint32_t wt = (uint32_t)(tap * 8192);
        const int ca = 2 * ks + kcA;
        const int cb = 2 * ks + kcB;
        ldsm4(fa[pb][0], rbA0 + ((ca ^ sA) << 4));
        ldsm4(fa[pb][1], rbA0 + 16 * 128 + ((ca ^ sA) << 4));
        ldsm4(fb[pb][0], rbB0 + wt + ((cb ^ sB) << 4));
        ldsm4(fb[pb][1], rbB1 + wt + ((cb ^ sB) << 4));
    };

    ldfrag(0, 0);
    #pragma unroll
    for (int it = 0; it < 36; ++it) {
        const int cur = it & 1;
        if (it < 35) ldfrag(it + 1, cur ^ 1);

        mma16(acc[0][0], fa[cur][0], fb[cur][0][0], fb[cur][0][2]);
        mma16(acc[1][0], fa[cur][1], fb[cur][0][0], fb[cur][0][2]);
        mma16(acc[0][1], fa[cur][0], fb[cur][0][1], fb[cur][0][3]);
        mma16(acc[1][1], fa[cur][1], fb[cur][0][1], fb[cur][0][3]);
        mma16(acc[0][2], fa[cur][0], fb[cur][1][0], fb[cur][1][2]);
        mma16(acc[1][2], fa[cur][1], fb[cur][1][0], fb[cur][1][2]);
        mma16(acc[0][3], fa[cur][0], fb[cur][1][1], fb[cur][1][3]);
        mma16(acc[1][3], fa[cur][1], fb[cur][1][1], fb[cur][1][3]);
    }

    // ---- epilogue: bias + store. acc rows = pixel lq (+8), cols = 2*lr (+1) ----
    const int i = i0 + r;
    #pragma unroll
    for (int mt = 0; mt < 2; ++mt) {
        int j = jb + mt * 16 + lq;
        float* o0 = out + (((size_t)(b * HH + i) * WW + j) * FF);
        float* o1 = o0 + 8 * FF;                // pixel +8
        #pragma unroll
        for (int nt = 0; nt < 4; ++nt) {
            int f = n0 + nt * 8 + 2 * lr;
            float2 v0 = make_float2(acc[mt][nt][0] + sbias[f], acc[mt][nt][1] + sbias[f + 1]);
            float2 v1 = make_float2(acc[mt][nt][2] + sbias[f], acc[mt][nt][3] + sbias[f + 1]);
            *(float2*)(o0 + f) = v0;
            *(float2*)(o1 + f) = v1;
        }
    }
}

extern "C" void kernel_launch(void* const* d_in, const int* in_sizes, int n_in,
                              void* d_out, int out_size) {
    const float* x    = (const float*)d_in[0];
    const float* kern = (const float*)d_in[1];
    const float* bias = (const float*)d_in[2];
    float* out = (float*)d_out;

    cudaFuncSetAttribute(conv_mma, cudaFuncAttributeMaxDynamicSharedMemorySize, SMEM_BYTES);

    wre3_kernel<<<(9 * FF * CIN + 255) / 256, 256>>>(kern);
    conv_mma<<<BATCH * 32, 256, SMEM_BYTES>>>(x, bias, out);
}